// round 9
// baseline (speedup 1.0000x reference)
#include <cuda_runtime.h>

#define UNITS   64
#define TT      512
#define BB      32
#define MOTOR   4
#define UNFOLDS 6
#define MROWS   (BB*TT)      // 16384

// ---------------- scratch (device globals: no allocation allowed) -----------
__device__ float  g_buf0[MROWS * 500];
__device__ float  g_buf1[MROWS * 500];
__device__ float  g_h20 [MROWS * 20];
__device__ float  g_o4  [MROWS * 4];
__device__ float2 g_sens[MROWS * UNITS];   // precomputed (wnum_s, wden_s)

__device__ __forceinline__ float fast_tanh(float x) {
    float r; asm("tanh.approx.f32 %0, %1;" : "=f"(r) : "f"(x)); return r;
}
__device__ __forceinline__ float fast_rcp(float x) {
    float r; asm("rcp.approx.f32 %0, %1;" : "=f"(r) : "f"(x)); return r;
}
__device__ __forceinline__ float fast_ex2(float x) {
    float r; asm("ex2.approx.f32 %0, %1;" : "=f"(r) : "f"(x)); return r;
}
__device__ __forceinline__ unsigned to_tf32(float x) {
    unsigned r; asm("cvt.rna.tf32.f32 %0, %1;" : "=r"(r) : "f"(x)); return r;
}

#define L2E 1.4426950408889634f

// ================= tf32 tensor-core GEMM: C = tanh(A@W + b) ==================
__device__ __forceinline__ void mma_tf32(float* d, const unsigned* a, const unsigned* b) {
    asm volatile(
        "mma.sync.aligned.m16n8k8.row.col.f32.tf32.tf32.f32 "
        "{%0,%1,%2,%3}, {%4,%5,%6,%7}, {%8,%9}, {%0,%1,%2,%3};"
        : "+f"(d[0]), "+f"(d[1]), "+f"(d[2]), "+f"(d[3])
        : "r"(a[0]), "r"(a[1]), "r"(a[2]), "r"(a[3]), "r"(b[0]), "r"(b[1]));
}

__global__ __launch_bounds__(256)
void gemm_tf32_tanh(const float* __restrict__ A, const float* __restrict__ W,
                    const float* __restrict__ bias, float* __restrict__ C,
                    int N, int K)
{
    __shared__ float As[2][128][20];   // [m][k], pad 16->20
    __shared__ float Bs[2][16][136];   // [k][n], pad 128->136

    const int tid  = threadIdx.x;
    const int lane = tid & 31;
    const int warp = tid >> 5;
    const int warp_m = (warp >> 2) * 64;
    const int warp_n = (warp & 3) * 32;
    const int block_row = blockIdx.y * 128;
    const int block_col = blockIdx.x * 128;

    const int a_r = tid >> 1;
    const int a_c = (tid & 1) * 8;
    const int b_k = tid >> 4;
    const int b_c = (tid & 15) * 8;

    const float* Arow = A + (size_t)(block_row + a_r) * K;

    float acc[4][4][4];
#pragma unroll
    for (int mt = 0; mt < 4; mt++)
#pragma unroll
        for (int nt = 0; nt < 4; nt++)
#pragma unroll
            for (int e = 0; e < 4; e++) acc[mt][nt][e] = 0.f;

    const int niter = (K + 15) / 16;
    float ra[8], rb[8];

#pragma unroll
    for (int u = 0; u < 8; u++) {
        int k = a_c + u;
        ra[u] = (k < K) ? Arow[k] : 0.f;
    }
#pragma unroll
    for (int u = 0; u < 8; u++) {
        int col = block_col + b_c + u;
        rb[u] = (b_k < K && col < N) ? W[(size_t)b_k * N + col] : 0.f;
    }
#pragma unroll
    for (int u = 0; u < 8; u++) As[0][a_r][a_c + u] = __uint_as_float(to_tf32(ra[u]));
#pragma unroll
    for (int u = 0; u < 8; u++) Bs[0][b_k][b_c + u] = __uint_as_float(to_tf32(rb[u]));
    __syncthreads();

    for (int it = 0; it < niter; it++) {
        const int s = it & 1;

        if (it + 1 < niter) {
            int k0 = (it + 1) * 16;
#pragma unroll
            for (int u = 0; u < 8; u++) {
                int k = k0 + a_c + u;
                ra[u] = (k < K) ? Arow[k] : 0.f;
            }
            int kb = k0 + b_k;
#pragma unroll
            for (int u = 0; u < 8; u++) {
                int col = block_col + b_c + u;
                rb[u] = (kb < K && col < N) ? W[(size_t)kb * N + col] : 0.f;
            }
        }

#pragma unroll
        for (int step = 0; step < 2; step++) {
            const int cb = step * 8;
            unsigned af[4][4], bf[4][2];
#pragma unroll
            for (int mt = 0; mt < 4; mt++) {
                int r0 = warp_m + mt * 16 + (lane >> 2);
                int c0 = cb + (lane & 3);
                af[mt][0] = __float_as_uint(As[s][r0][c0]);
                af[mt][1] = __float_as_uint(As[s][r0 + 8][c0]);
                af[mt][2] = __float_as_uint(As[s][r0][c0 + 4]);
                af[mt][3] = __float_as_uint(As[s][r0 + 8][c0 + 4]);
            }
#pragma unroll
            for (int nt = 0; nt < 4; nt++) {
                int n0 = warp_n + nt * 8 + (lane >> 2);
                bf[nt][0] = __float_as_uint(Bs[s][cb + (lane & 3)][n0]);
                bf[nt][1] = __float_as_uint(Bs[s][cb + (lane & 3) + 4][n0]);
            }
#pragma unroll
            for (int mt = 0; mt < 4; mt++)
#pragma unroll
                for (int nt = 0; nt < 4; nt++)
                    mma_tf32(acc[mt][nt], af[mt], bf[nt]);
        }

        if (it + 1 < niter) {
#pragma unroll
            for (int u = 0; u < 8; u++) As[s ^ 1][a_r][a_c + u] = __uint_as_float(to_tf32(ra[u]));
#pragma unroll
            for (int u = 0; u < 8; u++) Bs[s ^ 1][b_k][b_c + u] = __uint_as_float(to_tf32(rb[u]));
        }
        __syncthreads();
    }

#pragma unroll
    for (int mt = 0; mt < 4; mt++) {
        int r0 = block_row + warp_m + mt * 16 + (lane >> 2);
#pragma unroll
        for (int nt = 0; nt < 4; nt++) {
            int c0 = block_col + warp_n + nt * 8 + (lane & 3) * 2;
#pragma unroll
            for (int h = 0; h < 2; h++) {
                int rr = r0 + h * 8;
                float v0 = acc[mt][nt][h * 2 + 0];
                float v1 = acc[mt][nt][h * 2 + 1];
                if (c0 < N)     C[(size_t)rr * N + c0]     = fast_tanh(v0 + bias[c0]);
                if (c0 + 1 < N) C[(size_t)rr * N + c0 + 1] = fast_tanh(v1 + bias[c0 + 1]);
            }
        }
    }
}

// ---------------- SIMT fused GEMM (small-K layers) ---------------------------
template <int ACT>
__global__ __launch_bounds__(256, 2)
void gemm_bias_act(const float* __restrict__ A, const float* __restrict__ W,
                   const float* __restrict__ bias, float* __restrict__ C,
                   int N, int K)
{
    __shared__ float As[2][8][128];
    __shared__ float Bs[2][8][132];

    const int tid = threadIdx.x;
    const int block_row = blockIdx.y * 128;
    const int block_col = blockIdx.x * 128;
    const int tx = tid & 15, ty = tid >> 4;
    const int a_r = tid >> 1, a_c = (tid & 1) * 4;
    const int b_r = tid >> 5, b_c = (tid & 31) * 4;

    const float* Arow = A + (size_t)(block_row + a_r) * K;

    float acc[8][8];
#pragma unroll
    for (int i = 0; i < 8; i++)
#pragma unroll
        for (int j = 0; j < 8; j++) acc[i][j] = 0.f;

    const int niter = (K + 7) / 8;
    float ra[4], rb[4];
    {
#pragma unroll
        for (int u = 0; u < 4; u++) { int k = a_c + u; ra[u] = (k < K) ? Arow[k] : 0.f; }
#pragma unroll
        for (int u = 0; u < 4; u++) {
            int col = block_col + b_c + u;
            rb[u] = (b_r < K && col < N) ? W[(size_t)b_r * N + col] : 0.f;
        }
#pragma unroll
        for (int u = 0; u < 4; u++) As[0][a_c + u][a_r] = ra[u];
#pragma unroll
        for (int u = 0; u < 4; u++) Bs[0][b_r][b_c + u] = rb[u];
    }
    __syncthreads();

    for (int it = 0; it < niter; it++) {
        const int p = it & 1;
        if (it + 1 < niter) {
            int k0 = (it + 1) * 8;
#pragma unroll
            for (int u = 0; u < 4; u++) { int k = k0 + a_c + u; ra[u] = (k < K) ? Arow[k] : 0.f; }
            int kb = k0 + b_r;
#pragma unroll
            for (int u = 0; u < 4; u++) {
                int col = block_col + b_c + u;
                rb[u] = (kb < K && col < N) ? W[(size_t)kb * N + col] : 0.f;
            }
        }
#pragma unroll
        for (int kk = 0; kk < 8; kk++) {
            float ar[8], br[8];
#pragma unroll
            for (int i = 0; i < 8; i++) ar[i] = As[p][kk][ty * 8 + i];
#pragma unroll
            for (int j = 0; j < 8; j++) br[j] = Bs[p][kk][tx * 8 + j];
#pragma unroll
            for (int i = 0; i < 8; i++)
#pragma unroll
                for (int j = 0; j < 8; j++)
                    acc[i][j] += ar[i] * br[j];
        }
        if (it + 1 < niter) {
#pragma unroll
            for (int u = 0; u < 4; u++) As[p ^ 1][a_c + u][a_r] = ra[u];
#pragma unroll
            for (int u = 0; u < 4; u++) Bs[p ^ 1][b_r][b_c + u] = rb[u];
        }
        __syncthreads();
    }

#pragma unroll
    for (int i = 0; i < 8; i++) {
        int row = block_row + ty * 8 + i;
#pragma unroll
        for (int j = 0; j < 8; j++) {
            int col = block_col + tx * 8 + j;
            if (col < N) {
                float v = acc[i][j] + bias[col];
                if (ACT) v = fast_tanh(v);
                C[(size_t)row * N + col] = v;
            }
        }
    }
}

// ---------------- thin GEMM for N <= 32 --------------------------------------
template <int ACT>
__global__ __launch_bounds__(256)
void gemm_bias_act_thin(const float* __restrict__ A, const float* __restrict__ W,
                        const float* __restrict__ bias, float* __restrict__ C,
                        int N, int K)
{
    __shared__ float As[8][128];
    __shared__ float Bs[8][33];

    const int tid = threadIdx.x;
    const int block_row = blockIdx.y * 128;
    const int tx = tid & 7, ty = tid >> 3;
    const int a_r = tid >> 1, a_c = (tid & 1) * 4;
    const int b_k = tid >> 5, b_c = tid & 31;

    const float* Arow = A + (size_t)(block_row + a_r) * K;

    float acc[4][4];
#pragma unroll
    for (int i = 0; i < 4; i++)
#pragma unroll
        for (int j = 0; j < 4; j++) acc[i][j] = 0.f;

    for (int k0 = 0; k0 < K; k0 += 8) {
#pragma unroll
        for (int u = 0; u < 4; u++) {
            int k = k0 + a_c + u;
            As[a_c + u][a_r] = (k < K) ? Arow[k] : 0.f;
        }
        {
            int k = k0 + b_k;
            Bs[b_k][b_c] = (k < K && b_c < N) ? W[(size_t)k * N + b_c] : 0.f;
        }
        __syncthreads();
#pragma unroll
        for (int kk = 0; kk < 8; kk++) {
            float ar[4], br[4];
#pragma unroll
            for (int i = 0; i < 4; i++) ar[i] = As[kk][ty * 4 + i];
#pragma unroll
            for (int j = 0; j < 4; j++) br[j] = Bs[kk][tx * 4 + j];
#pragma unroll
            for (int i = 0; i < 4; i++)
#pragma unroll
                for (int j = 0; j < 4; j++)
                    acc[i][j] += ar[i] * br[j];
        }
        __syncthreads();
    }

#pragma unroll
    for (int i = 0; i < 4; i++) {
        int row = block_row + ty * 4 + i;
#pragma unroll
        for (int j = 0; j < 4; j++) {
            int col = tx * 4 + j;
            if (col < N) {
                float v = acc[i][j] + bias[col];
                if (ACT) v = fast_tanh(v);
                C[(size_t)row * N + col] = v;
            }
        }
    }
}

// ================= sensory precompute: (wnum_s, wden_s)[b,t,j] ===============
__global__ __launch_bounds__(256)
void sensory_pre(const float* __restrict__ h20, float2* __restrict__ sens,
                 const float* __restrict__ sw,   const float* __restrict__ smu,
                 const float* __restrict__ ssig, const float* __restrict__ serev,
                 const float* __restrict__ in_w, const float* __restrict__ in_b)
{
    __shared__ float sA[20][64], sB[20][64], sWe[20][64], sWr[20][64];
    __shared__ float hh[4][20];

    const int tid = threadIdx.x;
    const int bt0 = blockIdx.x * 4;

    for (int idx = tid; idx < 20 * 64; idx += 256) {
        int k = idx >> 6, j = idx & 63;
        float s_ = ssig[k * 64 + j];
        sA[k][j] = -in_w[k] * s_ * L2E;
        sB[k][j] = (smu[k * 64 + j] - in_b[k]) * s_ * L2E;
        float w_ = sw[k * 64 + j];
        sWr[k][j] = w_;
        sWe[k][j] = w_ * serev[k * 64 + j];
    }
    for (int idx = tid; idx < 80; idx += 256)
        hh[idx / 20][idx % 20] = h20[(size_t)bt0 * 20 + idx];
    __syncthreads();

    const int r = tid >> 6;
    const int j = tid & 63;
    float an = 0.f, ad = 0.f;
#pragma unroll
    for (int u = 0; u < 10; u++) {
        int k0 = 2 * u, k1 = 2 * u + 1;
        float a0 = fminf(fmaf(hh[r][k0], sA[k0][j], sB[k0][j]), 30.f);
        float a1 = fminf(fmaf(hh[r][k1], sA[k1][j], sB[k1][j]), 30.f);
        float q0 = 1.f + fast_ex2(a0);
        float q1 = 1.f + fast_ex2(a1);
        float rr = fast_rcp(q0 * q1);
        float nn = fmaf(sWe[k1][j], q0, sWe[k0][j] * q1);
        float dd = fmaf(sWr[k1][j], q0, sWr[k0][j] * q1);
        an = fmaf(rr, nn, an);
        ad = fmaf(rr, dd, ad);
    }
    sens[(size_t)(bt0 + r) * 64 + j] = make_float2(an, ad);
}

// ================= LTC scan: paired-reciprocal exact sigmoid =================
// 256 threads: j = tid>>2 (column), q = tid&3 owns 16 rows. sigma(x)=1/(1+e),
// e = ex2((mu-v)*sigma*L2E); one RCP per PAIR: per-unfold MUFU floor
// 48 instr/SMSP * rt8 = 384 cyc (vs tanh's 512). EX2/RCP computed inline per
// pair (no qe[] array) to stay within the no-spill register budget.
__global__ __launch_bounds__(256)
void ltc_scan(const float2* __restrict__ sens, float* __restrict__ o4,
              const float* __restrict__ gleak, const float* __restrict__ vleak,
              const float* __restrict__ cm,    const float* __restrict__ w,
              const float* __restrict__ mu,    const float* __restrict__ sigma,
              const float* __restrict__ erev,
              const float* __restrict__ out_w, const float* __restrict__ out_b)
{
    __shared__ float sv[2][UNITS];

    const int b   = blockIdx.x;
    const int tid = threadIdx.x;
    const int j   = tid >> 2;
    const int q   = tid & 3;

    // recurrent constants: e = ex2(fma(v, ca, cb)) = exp(-(v-mu)*sigma)
    float ca[16], cb[16], we[16], wr[16];
#pragma unroll
    for (int m = 0; m < 16; m++) {
        int i   = q * 16 + m;
        int idx = i * UNITS + j;
        float s_ = sigma[idx];
        ca[m] = -s_ * L2E;
        cb[m] = mu[idx] * s_ * L2E;
        wr[m] = w[idx];
        we[m] = wr[m] * erev[idx];
    }

    const float cmt  = cm[j] * (float)UNFOLDS;
    const float glv  = gleak[j] * vleak[j];
    const float den0 = cmt + gleak[j] + 1e-8f;
    float ow = 0.f, ob = 0.f;
    if (j < MOTOR) { ow = out_w[j]; ob = out_b[j]; }

    if (tid < UNITS) sv[0][tid] = 0.f;
    __syncthreads();

    const float2* srow = sens + (size_t)b * TT * 64 + j;
    float2 wv = srow[0];

    int   p  = 0;
    float vj = 0.f;

    for (int t = 0; t < TT; t++) {
        float2 wvn = (t + 1 < TT) ? srow[(size_t)(t + 1) * 64] : make_float2(0.f, 0.f);

#pragma unroll
        for (int uf = 0; uf < UNFOLDS; uf++) {
            const float4 v0 = *(const float4*)&sv[p][q * 16 + 0];
            const float4 v1 = *(const float4*)&sv[p][q * 16 + 4];
            const float4 v2 = *(const float4*)&sv[p][q * 16 + 8];
            const float4 v3 = *(const float4*)&sv[p][q * 16 + 12];
            float vr[16] = {v0.x, v0.y, v0.z, v0.w, v1.x, v1.y, v1.z, v1.w,
                            v2.x, v2.y, v2.z, v2.w, v3.x, v3.y, v3.z, v3.w};

            float an0 = 0.f, ad0 = 0.f, an1 = 0.f, ad1 = 0.f;
#pragma unroll
            for (int u = 0; u < 4; u++) {
                {   // pair (2u, 2u+1)
                    const int m0 = 2 * u, m1 = 2 * u + 1;
                    float a0 = fminf(fmaf(vr[m0], ca[m0], cb[m0]), 30.f);
                    float a1 = fminf(fmaf(vr[m1], ca[m1], cb[m1]), 30.f);
                    float q0 = 1.f + fast_ex2(a0);
                    float q1 = 1.f + fast_ex2(a1);
                    float rr = fast_rcp(q0 * q1);
                    float nn = fmaf(we[m1], q0, we[m0] * q1);
                    float dd = fmaf(wr[m1], q0, wr[m0] * q1);
                    an0 = fmaf(rr, nn, an0);
                    ad0 = fmaf(rr, dd, ad0);
                }
                {   // pair (8+2u, 8+2u+1)
                    const int m0 = 8 + 2 * u, m1 = 8 + 2 * u + 1;
                    float a0 = fminf(fmaf(vr[m0], ca[m0], cb[m0]), 30.f);
                    float a1 = fminf(fmaf(vr[m1], ca[m1], cb[m1]), 30.f);
                    float q0 = 1.f + fast_ex2(a0);
                    float q1 = 1.f + fast_ex2(a1);
                    float rr = fast_rcp(q0 * q1);
                    float nn = fmaf(we[m1], q0, we[m0] * q1);
                    float dd = fmaf(wr[m1], q0, wr[m0] * q1);
                    an1 = fmaf(rr, nn, an1);
                    ad1 = fmaf(rr, dd, ad1);
                }
            }
            float an = an0 + an1, ad = ad0 + ad1;
#pragma unroll
            for (int off = 1; off < 4; off <<= 1) {
                an += __shfl_xor_sync(0xffffffffu, an, off);
                ad += __shfl_xor_sync(0xffffffffu, ad, off);
            }
            float num = fmaf(cmt, vj, glv) + an + wv.x;
            float den = den0 + ad + wv.y;
            vj = num * fast_rcp(den);
            if (q == 0) sv[p ^ 1][j] = vj;
            __syncthreads();
            p ^= 1;
        }

        if (j < MOTOR && q == 0)
            o4[((size_t)b * TT + t) * MOTOR + j] = fmaf(vj, ow, ob);
        wv = wvn;
    }
}

// ---------------- launcher ---------------------------------------------------
extern "C" void kernel_launch(void* const* d_in, const int* in_sizes, int n_in,
                              void* d_out, int out_size)
{
    const float* x     = (const float*)d_in[0];
    const float* ew0   = (const float*)d_in[1];
    const float* eb0   = (const float*)d_in[2];
    const float* ew1   = (const float*)d_in[3];
    const float* eb1   = (const float*)d_in[4];
    const float* ew2   = (const float*)d_in[5];
    const float* eb2   = (const float*)d_in[6];
    const float* dw0   = (const float*)d_in[7];
    const float* db0   = (const float*)d_in[8];
    const float* dw1   = (const float*)d_in[9];
    const float* db1   = (const float*)d_in[10];
    const float* dw2   = (const float*)d_in[11];
    const float* db2   = (const float*)d_in[12];
    const float* gleak = (const float*)d_in[13];
    const float* vleak = (const float*)d_in[14];
    const float* cm    = (const float*)d_in[15];
    const float* w     = (const float*)d_in[16];
    const float* mu    = (const float*)d_in[17];
    const float* sigma = (const float*)d_in[18];
    const float* erev  = (const float*)d_in[19];
    const float* sw    = (const float*)d_in[20];
    const float* smu   = (const float*)d_in[21];
    const float* ssig  = (const float*)d_in[22];
    const float* serev = (const float*)d_in[23];
    const float* in_w  = (const float*)d_in[24];
    const float* in_b  = (const float*)d_in[25];
    const float* out_w = (const float*)d_in[26];
    const float* out_b = (const float*)d_in[27];
    float* out = (float*)d_out;

    float *buf0, *buf1, *h20, *o4;
    float2* sens;
    cudaGetSymbolAddress((void**)&buf0, g_buf0);
    cudaGetSymbolAddress((void**)&buf1, g_buf1);
    cudaGetSymbolAddress((void**)&h20,  g_h20);
    cudaGetSymbolAddress((void**)&o4,   g_o4);
    cudaGetSymbolAddress((void**)&sens, g_sens);

    dim3 blk(256);
    dim3 grid500(4, MROWS / 128);   // N=500 tiles
    dim3 gridthin(1, MROWS / 128);

    // encoder: 39 -> 500 -> 500 -> 20
    gemm_bias_act<1><<<grid500, blk>>>(x,    ew0, eb0, buf0, 500, 39);
    gemm_tf32_tanh  <<<grid500, blk>>>(buf0, ew1, eb1, buf1, 500, 500);
    gemm_bias_act_thin<0><<<gridthin, blk>>>(buf1, ew2, eb2, h20, 20, 500);

    // sensory precompute + LTC scan
    sensory_pre<<<MROWS / 4, blk>>>(h20, sens, sw, smu, ssig, serev, in_w, in_b);
    ltc_scan<<<BB, blk>>>(sens, o4, gleak, vleak, cm, w, mu, sigma, erev,
                          out_w, out_b);

    // decoder: 4 -> 500 -> 500 -> 30
    gemm_bias_act<1><<<grid500, blk>>>(o4,   dw0, db0, buf0, 500, 4);
    gemm_tf32_tanh  <<<grid500, blk>>>(buf0, dw1, db1, buf1, 500, 500);
    gemm_bias_act_thin<0><<<gridthin, blk>>>(buf1, dw2, db2, out, 30, 500);
}

// round 10
// speedup vs baseline: 1.4836x; 1.4836x over previous
#include <cuda_runtime.h>

#define UNITS   64
#define TT      512
#define BB      32
#define MOTOR   4
#define UNFOLDS 6
#define MROWS   (BB*TT)      // 16384

// ---------------- scratch (device globals: no allocation allowed) -----------
__device__ float  g_buf0[MROWS * 500];
__device__ float  g_buf1[MROWS * 500];
__device__ float  g_h20 [MROWS * 20];
__device__ float  g_o4  [MROWS * 4];
__device__ float2 g_sens[MROWS * UNITS];   // precomputed (wnum_s, wden_s)

__device__ __forceinline__ float fast_tanh(float x) {
    float r; asm("tanh.approx.f32 %0, %1;" : "=f"(r) : "f"(x)); return r;
}
__device__ __forceinline__ float fast_rcp(float x) {
    float r; asm("rcp.approx.f32 %0, %1;" : "=f"(r) : "f"(x)); return r;
}
__device__ __forceinline__ float fast_ex2(float x) {
    float r; asm("ex2.approx.f32 %0, %1;" : "=f"(r) : "f"(x)); return r;
}
__device__ __forceinline__ unsigned to_tf32(float x) {
    unsigned r; asm("cvt.rna.tf32.f32 %0, %1;" : "=r"(r) : "f"(x)); return r;
}

#define L2E 1.4426950408889634f

// ================= tf32 tensor-core GEMM: C = tanh(A@W + b) ==================
// 128x128 CTA tile, BK=16, 8 warps (2x4), warp tile 64x32, mma.m16n8k8.tf32.
// 2 CTAs/SM for latency hiding of the scalar-LDS fragment loads.
__device__ __forceinline__ void mma_tf32(float* d, const unsigned* a, const unsigned* b) {
    asm volatile(
        "mma.sync.aligned.m16n8k8.row.col.f32.tf32.tf32.f32 "
        "{%0,%1,%2,%3}, {%4,%5,%6,%7}, {%8,%9}, {%0,%1,%2,%3};"
        : "+f"(d[0]), "+f"(d[1]), "+f"(d[2]), "+f"(d[3])
        : "r"(a[0]), "r"(a[1]), "r"(a[2]), "r"(a[3]), "r"(b[0]), "r"(b[1]));
}

__global__ __launch_bounds__(256, 2)
void gemm_tf32_tanh(const float* __restrict__ A, const float* __restrict__ W,
                    const float* __restrict__ bias, float* __restrict__ C,
                    int N, int K)
{
    __shared__ float As[2][128][20];   // [m][k], pad 16->20
    __shared__ float Bs[2][16][136];   // [k][n], pad 128->136

    const int tid  = threadIdx.x;
    const int lane = tid & 31;
    const int warp = tid >> 5;
    const int warp_m = (warp >> 2) * 64;
    const int warp_n = (warp & 3) * 32;
    const int block_row = blockIdx.y * 128;
    const int block_col = blockIdx.x * 128;

    const int a_r = tid >> 1;
    const int a_c = (tid & 1) * 8;
    const int b_k = tid >> 4;
    const int b_c = (tid & 15) * 8;

    const float* Arow = A + (size_t)(block_row + a_r) * K;

    float acc[4][4][4];
#pragma unroll
    for (int mt = 0; mt < 4; mt++)
#pragma unroll
        for (int nt = 0; nt < 4; nt++)
#pragma unroll
            for (int e = 0; e < 4; e++) acc[mt][nt][e] = 0.f;

    const int niter = (K + 15) / 16;
    float ra[8], rb[8];

#pragma unroll
    for (int u = 0; u < 8; u++) {
        int k = a_c + u;
        ra[u] = (k < K) ? Arow[k] : 0.f;
    }
#pragma unroll
    for (int u = 0; u < 8; u++) {
        int col = block_col + b_c + u;
        rb[u] = (b_k < K && col < N) ? W[(size_t)b_k * N + col] : 0.f;
    }
#pragma unroll
    for (int u = 0; u < 8; u++) As[0][a_r][a_c + u] = __uint_as_float(to_tf32(ra[u]));
#pragma unroll
    for (int u = 0; u < 8; u++) Bs[0][b_k][b_c + u] = __uint_as_float(to_tf32(rb[u]));
    __syncthreads();

    for (int it = 0; it < niter; it++) {
        const int s = it & 1;

        if (it + 1 < niter) {
            int k0 = (it + 1) * 16;
#pragma unroll
            for (int u = 0; u < 8; u++) {
                int k = k0 + a_c + u;
                ra[u] = (k < K) ? Arow[k] : 0.f;
            }
            int kb = k0 + b_k;
#pragma unroll
            for (int u = 0; u < 8; u++) {
                int col = block_col + b_c + u;
                rb[u] = (kb < K && col < N) ? W[(size_t)kb * N + col] : 0.f;
            }
        }

#pragma unroll
        for (int step = 0; step < 2; step++) {
            const int cb = step * 8;
            unsigned af[4][4], bf[4][2];
#pragma unroll
            for (int mt = 0; mt < 4; mt++) {
                int r0 = warp_m + mt * 16 + (lane >> 2);
                int c0 = cb + (lane & 3);
                af[mt][0] = __float_as_uint(As[s][r0][c0]);
                af[mt][1] = __float_as_uint(As[s][r0 + 8][c0]);
                af[mt][2] = __float_as_uint(As[s][r0][c0 + 4]);
                af[mt][3] = __float_as_uint(As[s][r0 + 8][c0 + 4]);
            }
#pragma unroll
            for (int nt = 0; nt < 4; nt++) {
                int n0 = warp_n + nt * 8 + (lane >> 2);
                bf[nt][0] = __float_as_uint(Bs[s][cb + (lane & 3)][n0]);
                bf[nt][1] = __float_as_uint(Bs[s][cb + (lane & 3) + 4][n0]);
            }
#pragma unroll
            for (int mt = 0; mt < 4; mt++)
#pragma unroll
                for (int nt = 0; nt < 4; nt++)
                    mma_tf32(acc[mt][nt], af[mt], bf[nt]);
        }

        if (it + 1 < niter) {
#pragma unroll
            for (int u = 0; u < 8; u++) As[s ^ 1][a_r][a_c + u] = __uint_as_float(to_tf32(ra[u]));
#pragma unroll
            for (int u = 0; u < 8; u++) Bs[s ^ 1][b_k][b_c + u] = __uint_as_float(to_tf32(rb[u]));
        }
        __syncthreads();
    }

#pragma unroll
    for (int mt = 0; mt < 4; mt++) {
        int r0 = block_row + warp_m + mt * 16 + (lane >> 2);
#pragma unroll
        for (int nt = 0; nt < 4; nt++) {
            int c0 = block_col + warp_n + nt * 8 + (lane & 3) * 2;
#pragma unroll
            for (int h = 0; h < 2; h++) {
                int rr = r0 + h * 8;
                float v0 = acc[mt][nt][h * 2 + 0];
                float v1 = acc[mt][nt][h * 2 + 1];
                if (c0 < N)     C[(size_t)rr * N + c0]     = fast_tanh(v0 + bias[c0]);
                if (c0 + 1 < N) C[(size_t)rr * N + c0 + 1] = fast_tanh(v1 + bias[c0 + 1]);
            }
        }
    }
}

// ---------------- SIMT fused GEMM (small-K layers) ---------------------------
template <int ACT>
__global__ __launch_bounds__(256, 2)
void gemm_bias_act(const float* __restrict__ A, const float* __restrict__ W,
                   const float* __restrict__ bias, float* __restrict__ C,
                   int N, int K)
{
    __shared__ float As[2][8][128];
    __shared__ float Bs[2][8][132];

    const int tid = threadIdx.x;
    const int block_row = blockIdx.y * 128;
    const int block_col = blockIdx.x * 128;
    const int tx = tid & 15, ty = tid >> 4;
    const int a_r = tid >> 1, a_c = (tid & 1) * 4;
    const int b_r = tid >> 5, b_c = (tid & 31) * 4;

    const float* Arow = A + (size_t)(block_row + a_r) * K;

    float acc[8][8];
#pragma unroll
    for (int i = 0; i < 8; i++)
#pragma unroll
        for (int j = 0; j < 8; j++) acc[i][j] = 0.f;

    const int niter = (K + 7) / 8;
    float ra[4], rb[4];
    {
#pragma unroll
        for (int u = 0; u < 4; u++) { int k = a_c + u; ra[u] = (k < K) ? Arow[k] : 0.f; }
#pragma unroll
        for (int u = 0; u < 4; u++) {
            int col = block_col + b_c + u;
            rb[u] = (b_r < K && col < N) ? W[(size_t)b_r * N + col] : 0.f;
        }
#pragma unroll
        for (int u = 0; u < 4; u++) As[0][a_c + u][a_r] = ra[u];
#pragma unroll
        for (int u = 0; u < 4; u++) Bs[0][b_r][b_c + u] = rb[u];
    }
    __syncthreads();

    for (int it = 0; it < niter; it++) {
        const int p = it & 1;
        if (it + 1 < niter) {
            int k0 = (it + 1) * 8;
#pragma unroll
            for (int u = 0; u < 4; u++) { int k = k0 + a_c + u; ra[u] = (k < K) ? Arow[k] : 0.f; }
            int kb = k0 + b_r;
#pragma unroll
            for (int u = 0; u < 4; u++) {
                int col = block_col + b_c + u;
                rb[u] = (kb < K && col < N) ? W[(size_t)kb * N + col] : 0.f;
            }
        }
#pragma unroll
        for (int kk = 0; kk < 8; kk++) {
            float ar[8], br[8];
#pragma unroll
            for (int i = 0; i < 8; i++) ar[i] = As[p][kk][ty * 8 + i];
#pragma unroll
            for (int j = 0; j < 8; j++) br[j] = Bs[p][kk][tx * 8 + j];
#pragma unroll
            for (int i = 0; i < 8; i++)
#pragma unroll
                for (int j = 0; j < 8; j++)
                    acc[i][j] += ar[i] * br[j];
        }
        if (it + 1 < niter) {
#pragma unroll
            for (int u = 0; u < 4; u++) As[p ^ 1][a_c + u][a_r] = ra[u];
#pragma unroll
            for (int u = 0; u < 4; u++) Bs[p ^ 1][b_r][b_c + u] = rb[u];
        }
        __syncthreads();
    }

#pragma unroll
    for (int i = 0; i < 8; i++) {
        int row = block_row + ty * 8 + i;
#pragma unroll
        for (int j = 0; j < 8; j++) {
            int col = block_col + tx * 8 + j;
            if (col < N) {
                float v = acc[i][j] + bias[col];
                if (ACT) v = fast_tanh(v);
                C[(size_t)row * N + col] = v;
            }
        }
    }
}

// ---------------- thin GEMM for N <= 32 (double-buffered) --------------------
template <int ACT>
__global__ __launch_bounds__(256, 2)
void gemm_bias_act_thin(const float* __restrict__ A, const float* __restrict__ W,
                        const float* __restrict__ bias, float* __restrict__ C,
                        int N, int K)
{
    __shared__ float As[2][8][128];
    __shared__ float Bs[2][8][33];

    const int tid = threadIdx.x;
    const int block_row = blockIdx.y * 128;
    const int tx = tid & 7, ty = tid >> 3;
    const int a_r = tid >> 1, a_c = (tid & 1) * 4;
    const int b_k = tid >> 5, b_c = tid & 31;

    const float* Arow = A + (size_t)(block_row + a_r) * K;

    float acc[4][4];
#pragma unroll
    for (int i = 0; i < 4; i++)
#pragma unroll
        for (int j = 0; j < 4; j++) acc[i][j] = 0.f;

    const int niter = (K + 7) / 8;
    float ra[4], rb;
    {
#pragma unroll
        for (int u = 0; u < 4; u++) { int k = a_c + u; ra[u] = (k < K) ? Arow[k] : 0.f; }
        rb = (b_k < K && b_c < N) ? W[(size_t)b_k * N + b_c] : 0.f;
#pragma unroll
        for (int u = 0; u < 4; u++) As[0][a_c + u][a_r] = ra[u];
        Bs[0][b_k][b_c] = rb;
    }
    __syncthreads();

    for (int it = 0; it < niter; it++) {
        const int p = it & 1;
        if (it + 1 < niter) {
            int k0 = (it + 1) * 8;
#pragma unroll
            for (int u = 0; u < 4; u++) { int k = k0 + a_c + u; ra[u] = (k < K) ? Arow[k] : 0.f; }
            int kb = k0 + b_k;
            rb = (kb < K && b_c < N) ? W[(size_t)kb * N + b_c] : 0.f;
        }
#pragma unroll
        for (int kk = 0; kk < 8; kk++) {
            float ar[4], br[4];
#pragma unroll
            for (int i = 0; i < 4; i++) ar[i] = As[p][kk][ty * 4 + i];
#pragma unroll
            for (int j = 0; j < 4; j++) br[j] = Bs[p][kk][tx * 4 + j];
#pragma unroll
            for (int i = 0; i < 4; i++)
#pragma unroll
                for (int j = 0; j < 4; j++)
                    acc[i][j] += ar[i] * br[j];
        }
        if (it + 1 < niter) {
#pragma unroll
            for (int u = 0; u < 4; u++) As[p ^ 1][a_c + u][a_r] = ra[u];
            Bs[p ^ 1][b_k][b_c] = rb;
        }
        __syncthreads();
    }

#pragma unroll
    for (int i = 0; i < 4; i++) {
        int row = block_row + ty * 4 + i;
#pragma unroll
        for (int j = 0; j < 4; j++) {
            int col = tx * 4 + j;
            if (col < N) {
                float v = acc[i][j] + bias[col];
                if (ACT) v = fast_tanh(v);
                C[(size_t)row * N + col] = v;
            }
        }
    }
}

// ================= sensory precompute: (wnum_s, wden_s)[b,t,j] ===============
__global__ __launch_bounds__(256)
void sensory_pre(const float* __restrict__ h20, float2* __restrict__ sens,
                 const float* __restrict__ sw,   const float* __restrict__ smu,
                 const float* __restrict__ ssig, const float* __restrict__ serev,
                 const float* __restrict__ in_w, const float* __restrict__ in_b)
{
    __shared__ float sA[20][64], sB[20][64], sWe[20][64], sWr[20][64];
    __shared__ float hh[4][20];

    const int tid = threadIdx.x;
    const int bt0 = blockIdx.x * 4;

    for (int idx = tid; idx < 20 * 64; idx += 256) {
        int k = idx >> 6, j = idx & 63;
        float s_ = ssig[k * 64 + j];
        sA[k][j] = -in_w[k] * s_ * L2E;
        sB[k][j] = (smu[k * 64 + j] - in_b[k]) * s_ * L2E;
        float w_ = sw[k * 64 + j];
        sWr[k][j] = w_;
        sWe[k][j] = w_ * serev[k * 64 + j];
    }
    for (int idx = tid; idx < 80; idx += 256)
        hh[idx / 20][idx % 20] = h20[(size_t)bt0 * 20 + idx];
    __syncthreads();

    const int r = tid >> 6;
    const int j = tid & 63;
    float an = 0.f, ad = 0.f;
#pragma unroll
    for (int u = 0; u < 10; u++) {
        int k0 = 2 * u, k1 = 2 * u + 1;
        float a0 = fminf(fmaf(hh[r][k0], sA[k0][j], sB[k0][j]), 30.f);
        float a1 = fminf(fmaf(hh[r][k1], sA[k1][j], sB[k1][j]), 30.f);
        float q0 = 1.f + fast_ex2(a0);
        float q1 = 1.f + fast_ex2(a1);
        float rr = fast_rcp(q0 * q1);
        float nn = fmaf(sWe[k1][j], q0, sWe[k0][j] * q1);
        float dd = fmaf(sWr[k1][j], q0, sWr[k0][j] * q1);
        an = fmaf(rr, nn, an);
        ad = fmaf(rr, dd, ad);
    }
    sens[(size_t)(bt0 + r) * 64 + j] = make_float2(an, ad);
}

// ================= LTC scan (R8 winner: tanh sigmoid, precomputed sensory) ===
// 256 threads: j = tid>>2 (column), q = tid&3 owns 16 rows.
// sigmoid(x) = 0.5 + 0.5*tanh(0.5*x); constant halves folded (recurrent);
// sensory sums read from g_sens with one-step prefetch.
__global__ __launch_bounds__(256)
void ltc_scan(const float2* __restrict__ sens, float* __restrict__ o4,
              const float* __restrict__ gleak, const float* __restrict__ vleak,
              const float* __restrict__ cm,    const float* __restrict__ w,
              const float* __restrict__ mu,    const float* __restrict__ sigma,
              const float* __restrict__ erev,
              const float* __restrict__ out_w, const float* __restrict__ out_b)
{
    __shared__ float sv[2][UNITS];

    const int b   = blockIdx.x;
    const int tid = threadIdx.x;
    const int j   = tid >> 2;
    const int q   = tid & 3;

    // recurrent constants, tanh-folded: 0.5*(v-mu)*sigma = v*ha[m] - hb[m]
    float ha[16], hb[16], we2[16], wr2[16];
    float cnum = 0.f, cden = 0.f;          // 0.5*sum(w*erev), 0.5*sum(w)
#pragma unroll
    for (int m = 0; m < 16; m++) {
        int i   = q * 16 + m;
        int idx = i * UNITS + j;
        float s_ = sigma[idx];
        ha[m] = 0.5f * s_;
        hb[m] = 0.5f * mu[idx] * s_;
        float wv = 0.5f * w[idx];
        wr2[m] = wv;
        we2[m] = wv * erev[idx];
        cnum += we2[m];
        cden += wr2[m];
    }
#pragma unroll
    for (int off = 1; off < 4; off <<= 1) {
        cnum += __shfl_xor_sync(0xffffffffu, cnum, off);
        cden += __shfl_xor_sync(0xffffffffu, cden, off);
    }

    const float cmt    = cm[j] * (float)UNFOLDS;        // cm / (1/6)
    const float addnum = gleak[j] * vleak[j] + cnum;
    const float denbas = cmt + gleak[j] + cden + 1e-8f;
    float ow = 0.f, ob = 0.f;
    if (j < MOTOR) { ow = out_w[j]; ob = out_b[j]; }

    if (tid < UNITS) sv[0][tid] = 0.f;
    __syncthreads();

    const float2* srow = sens + (size_t)b * TT * 64 + j;
    float2 wv = srow[0];

    int   p  = 0;
    float vj = 0.f;

    for (int t = 0; t < TT; t++) {
        float2 wvn = (t + 1 < TT) ? srow[(size_t)(t + 1) * 64] : make_float2(0.f, 0.f);

#pragma unroll
        for (int uf = 0; uf < UNFOLDS; uf++) {
            const float4 v0 = *(const float4*)&sv[p][q * 16 + 0];
            const float4 v1 = *(const float4*)&sv[p][q * 16 + 4];
            const float4 v2 = *(const float4*)&sv[p][q * 16 + 8];
            const float4 v3 = *(const float4*)&sv[p][q * 16 + 12];
            float vr[16] = {v0.x, v0.y, v0.z, v0.w, v1.x, v1.y, v1.z, v1.w,
                            v2.x, v2.y, v2.z, v2.w, v3.x, v3.y, v3.z, v3.w};

            float an0 = 0.f, ad0 = 0.f, an1 = 0.f, ad1 = 0.f;
#pragma unroll
            for (int m = 0; m < 8; m++) {
                float t0 = fast_tanh(fmaf(vr[m],     ha[m],     -hb[m]));
                float t1 = fast_tanh(fmaf(vr[m + 8], ha[m + 8], -hb[m + 8]));
                an0 = fmaf(we2[m],     t0, an0);
                ad0 = fmaf(wr2[m],     t0, ad0);
                an1 = fmaf(we2[m + 8], t1, an1);
                ad1 = fmaf(wr2[m + 8], t1, ad1);
            }
            float an = an0 + an1, ad = ad0 + ad1;
#pragma unroll
            for (int off = 1; off < 4; off <<= 1) {
                an += __shfl_xor_sync(0xffffffffu, an, off);
                ad += __shfl_xor_sync(0xffffffffu, ad, off);
            }
            float num = fmaf(cmt, vj, addnum) + an + wv.x;
            float den = denbas + ad + wv.y;
            vj = num * fast_rcp(den);
            if (q == 0) sv[p ^ 1][j] = vj;
            __syncthreads();
            p ^= 1;
        }

        if (j < MOTOR && q == 0)
            o4[((size_t)b * TT + t) * MOTOR + j] = fmaf(vj, ow, ob);
        wv = wvn;
    }
}

// ---------------- launcher ---------------------------------------------------
extern "C" void kernel_launch(void* const* d_in, const int* in_sizes, int n_in,
                              void* d_out, int out_size)
{
    const float* x     = (const float*)d_in[0];
    const float* ew0   = (const float*)d_in[1];
    const float* eb0   = (const float*)d_in[2];
    const float* ew1   = (const float*)d_in[3];
    const float* eb1   = (const float*)d_in[4];
    const float* ew2   = (const float*)d_in[5];
    const float* eb2   = (const float*)d_in[6];
    const float* dw0   = (const float*)d_in[7];
    const float* db0   = (const float*)d_in[8];
    const float* dw1   = (const float*)d_in[9];
    const float* db1   = (const float*)d_in[10];
    const float* dw2   = (const float*)d_in[11];
    const float* db2   = (const float*)d_in[12];
    const float* gleak = (const float*)d_in[13];
    const float* vleak = (const float*)d_in[14];
    const float* cm    = (const float*)d_in[15];
    const float* w     = (const float*)d_in[16];
    const float* mu    = (const float*)d_in[17];
    const float* sigma = (const float*)d_in[18];
    const float* erev  = (const float*)d_in[19];
    const float* sw    = (const float*)d_in[20];
    const float* smu   = (const float*)d_in[21];
    const float* ssig  = (const float*)d_in[22];
    const float* serev = (const float*)d_in[23];
    const float* in_w  = (const float*)d_in[24];
    const float* in_b  = (const float*)d_in[25];
    const float* out_w = (const float*)d_in[26];
    const float* out_b = (const float*)d_in[27];
    float* out = (float*)d_out;

    float *buf0, *buf1, *h20, *o4;
    float2* sens;
    cudaGetSymbolAddress((void**)&buf0, g_buf0);
    cudaGetSymbolAddress((void**)&buf1, g_buf1);
    cudaGetSymbolAddress((void**)&h20,  g_h20);
    cudaGetSymbolAddress((void**)&o4,   g_o4);
    cudaGetSymbolAddress((void**)&sens, g_sens);

    dim3 blk(256);
    dim3 grid500(4, MROWS / 128);   // N=500 tiles
    dim3 gridthin(1, MROWS / 128);

    // encoder: 39 -> 500 -> 500 -> 20
    gemm_bias_act<1><<<grid500, blk>>>(x,    ew0, eb0, buf0, 500, 39);
    gemm_tf32_tanh  <<<grid500, blk>>>(buf0, ew1, eb1, buf1, 500, 500);
    gemm_bias_act_thin<0><<<gridthin, blk>>>(buf1, ew2, eb2, h20, 20, 500);

    // sensory precompute + LTC scan
    sensory_pre<<<MROWS / 4, blk>>>(h20, sens, sw, smu, ssig, serev, in_w, in_b);
    ltc_scan<<<BB, blk>>>(sens, o4, gleak, vleak, cm, w, mu, sigma, erev,
                          out_w, out_b);

    // decoder: 4 -> 500 -> 500 -> 30
    gemm_bias_act<1><<<grid500, blk>>>(o4,   dw0, db0, buf0, 500, 4);
    gemm_tf32_tanh  <<<grid500, blk>>>(buf0, dw1, db1, buf1, 500, 500);
    gemm_bias_act_thin<0><<<gridthin, blk>>>(buf1, dw2, db2, out, 30, 500);
}

// round 12
// speedup vs baseline: 1.4873x; 1.0025x over previous
#include <cuda_runtime.h>

#define UNITS   64
#define TT      512
#define BB      32
#define MOTOR   4
#define UNFOLDS 6
#define MROWS   (BB*TT)      // 16384
#define NCH     4
#define TC      (TT/NCH)     // 128 timesteps per chunk

// ---------------- scratch (device globals: no allocation allowed) -----------
__device__ float  g_buf0[MROWS * 500];    // encoder intermediates
__device__ float  g_buf1[MROWS * 500];
__device__ float  g_dbuf0[MROWS * 500];   // decoder intermediates (separate:
__device__ float  g_dbuf1[MROWS * 500];   //  encoder/decoder chunks overlap)
__device__ float  g_h20 [MROWS * 20];
__device__ float  g_o4  [MROWS * 4];
__device__ float  g_v   [BB * UNITS];     // scan state between chunks
__device__ float2 g_sens[MROWS * UNITS];  // precomputed (wnum_s, wden_s)

__device__ __forceinline__ float fast_tanh(float x) {
    float r; asm("tanh.approx.f32 %0, %1;" : "=f"(r) : "f"(x)); return r;
}
__device__ __forceinline__ float fast_rcp(float x) {
    float r; asm("rcp.approx.f32 %0, %1;" : "=f"(r) : "f"(x)); return r;
}
__device__ __forceinline__ float fast_ex2(float x) {
    float r; asm("ex2.approx.f32 %0, %1;" : "=f"(r) : "f"(x)); return r;
}
__device__ __forceinline__ unsigned to_tf32(float x) {
    unsigned r; asm("cvt.rna.tf32.f32 %0, %1;" : "=r"(r) : "f"(x)); return r;
}

#define L2E 1.4426950408889634f

// ================= tf32 legacy-MMA GEMM: C = tanh(A@W + b) ===================
// 128x128 tile per (chunk-segment), BK=16, 8 warps, chunk rows via
// block_row = rowbase + blockIdx.y * TT (one 128-row tile per batch).
__device__ __forceinline__ void mma_tf32(float* d, const unsigned* a, const unsigned* b) {
    asm volatile(
        "mma.sync.aligned.m16n8k8.row.col.f32.tf32.tf32.f32 "
        "{%0,%1,%2,%3}, {%4,%5,%6,%7}, {%8,%9}, {%0,%1,%2,%3};"
        : "+f"(d[0]), "+f"(d[1]), "+f"(d[2]), "+f"(d[3])
        : "r"(a[0]), "r"(a[1]), "r"(a[2]), "r"(a[3]), "r"(b[0]), "r"(b[1]));
}

__global__ __launch_bounds__(256, 2)
void gemm_tf32_tanh(const float* __restrict__ A, const float* __restrict__ W,
                    const float* __restrict__ bias, float* __restrict__ C,
                    int N, int K, int rowbase)
{
    __shared__ float As[2][128][20];
    __shared__ float Bs[2][16][136];

    const int tid  = threadIdx.x;
    const int lane = tid & 31;
    const int warp = tid >> 5;
    const int warp_m = (warp >> 2) * 64;
    const int warp_n = (warp & 3) * 32;
    const int block_row = rowbase + blockIdx.y * TT;
    const int block_col = blockIdx.x * 128;

    const int a_r = tid >> 1;
    const int a_c = (tid & 1) * 8;
    const int b_k = tid >> 4;
    const int b_c = (tid & 15) * 8;

    const float* Arow = A + (size_t)(block_row + a_r) * K;

    float acc[4][4][4];
#pragma unroll
    for (int mt = 0; mt < 4; mt++)
#pragma unroll
        for (int nt = 0; nt < 4; nt++)
#pragma unroll
            for (int e = 0; e < 4; e++) acc[mt][nt][e] = 0.f;

    const int niter = (K + 15) / 16;
    float ra[8], rb[8];

#pragma unroll
    for (int u = 0; u < 8; u++) { int k = a_c + u; ra[u] = (k < K) ? Arow[k] : 0.f; }
#pragma unroll
    for (int u = 0; u < 8; u++) {
        int col = block_col + b_c + u;
        rb[u] = (b_k < K && col < N) ? W[(size_t)b_k * N + col] : 0.f;
    }
#pragma unroll
    for (int u = 0; u < 8; u++) As[0][a_r][a_c + u] = __uint_as_float(to_tf32(ra[u]));
#pragma unroll
    for (int u = 0; u < 8; u++) Bs[0][b_k][b_c + u] = __uint_as_float(to_tf32(rb[u]));
    __syncthreads();

    for (int it = 0; it < niter; it++) {
        const int s = it & 1;

        if (it + 1 < niter) {
            int k0 = (it + 1) * 16;
#pragma unroll
            for (int u = 0; u < 8; u++) { int k = k0 + a_c + u; ra[u] = (k < K) ? Arow[k] : 0.f; }
            int kb = k0 + b_k;
#pragma unroll
            for (int u = 0; u < 8; u++) {
                int col = block_col + b_c + u;
                rb[u] = (kb < K && col < N) ? W[(size_t)kb * N + col] : 0.f;
            }
        }

#pragma unroll
        for (int step = 0; step < 2; step++) {
            const int cb = step * 8;
            unsigned af[4][4], bf[4][2];
#pragma unroll
            for (int mt = 0; mt < 4; mt++) {
                int r0 = warp_m + mt * 16 + (lane >> 2);
                int c0 = cb + (lane & 3);
                af[mt][0] = __float_as_uint(As[s][r0][c0]);
                af[mt][1] = __float_as_uint(As[s][r0 + 8][c0]);
                af[mt][2] = __float_as_uint(As[s][r0][c0 + 4]);
                af[mt][3] = __float_as_uint(As[s][r0 + 8][c0 + 4]);
            }
#pragma unroll
            for (int nt = 0; nt < 4; nt++) {
                int n0 = warp_n + nt * 8 + (lane >> 2);
                bf[nt][0] = __float_as_uint(Bs[s][cb + (lane & 3)][n0]);
                bf[nt][1] = __float_as_uint(Bs[s][cb + (lane & 3) + 4][n0]);
            }
#pragma unroll
            for (int mt = 0; mt < 4; mt++)
#pragma unroll
                for (int nt = 0; nt < 4; nt++)
                    mma_tf32(acc[mt][nt], af[mt], bf[nt]);
        }

        if (it + 1 < niter) {
#pragma unroll
            for (int u = 0; u < 8; u++) As[s ^ 1][a_r][a_c + u] = __uint_as_float(to_tf32(ra[u]));
#pragma unroll
            for (int u = 0; u < 8; u++) Bs[s ^ 1][b_k][b_c + u] = __uint_as_float(to_tf32(rb[u]));
        }
        __syncthreads();
    }

#pragma unroll
    for (int mt = 0; mt < 4; mt++) {
        int r0 = block_row + warp_m + mt * 16 + (lane >> 2);
#pragma unroll
        for (int nt = 0; nt < 4; nt++) {
            int c0 = block_col + warp_n + nt * 8 + (lane & 3) * 2;
#pragma unroll
            for (int h = 0; h < 2; h++) {
                int rr = r0 + h * 8;
                float v0 = acc[mt][nt][h * 2 + 0];
                float v1 = acc[mt][nt][h * 2 + 1];
                if (c0 < N)     C[(size_t)rr * N + c0]     = fast_tanh(v0 + bias[c0]);
                if (c0 + 1 < N) C[(size_t)rr * N + c0 + 1] = fast_tanh(v1 + bias[c0 + 1]);
            }
        }
    }
}

// ---------------- SIMT fused GEMM (small-K layers) ---------------------------
template <int ACT>
__global__ __launch_bounds__(256, 2)
void gemm_bias_act(const float* __restrict__ A, const float* __restrict__ W,
                   const float* __restrict__ bias, float* __restrict__ C,
                   int N, int K, int rowbase)
{
    __shared__ float As[2][8][128];
    __shared__ float Bs[2][8][132];

    const int tid = threadIdx.x;
    const int block_row = rowbase + blockIdx.y * TT;
    const int block_col = blockIdx.x * 128;
    const int tx = tid & 15, ty = tid >> 4;
    const int a_r = tid >> 1, a_c = (tid & 1) * 4;
    const int b_r = tid >> 5, b_c = (tid & 31) * 4;

    const float* Arow = A + (size_t)(block_row + a_r) * K;

    float acc[8][8];
#pragma unroll
    for (int i = 0; i < 8; i++)
#pragma unroll
        for (int j = 0; j < 8; j++) acc[i][j] = 0.f;

    const int niter = (K + 7) / 8;
    float ra[4], rb[4];
    {
#pragma unroll
        for (int u = 0; u < 4; u++) { int k = a_c + u; ra[u] = (k < K) ? Arow[k] : 0.f; }
#pragma unroll
        for (int u = 0; u < 4; u++) {
            int col = block_col + b_c + u;
            rb[u] = (b_r < K && col < N) ? W[(size_t)b_r * N + col] : 0.f;
        }
#pragma unroll
        for (int u = 0; u < 4; u++) As[0][a_c + u][a_r] = ra[u];
#pragma unroll
        for (int u = 0; u < 4; u++) Bs[0][b_r][b_c + u] = rb[u];
    }
    __syncthreads();

    for (int it = 0; it < niter; it++) {
        const int p = it & 1;
        if (it + 1 < niter) {
            int k0 = (it + 1) * 8;
#pragma unroll
            for (int u = 0; u < 4; u++) { int k = k0 + a_c + u; ra[u] = (k < K) ? Arow[k] : 0.f; }
            int kb = k0 + b_r;
#pragma unroll
            for (int u = 0; u < 4; u++) {
                int col = block_col + b_c + u;
                rb[u] = (kb < K && col < N) ? W[(size_t)kb * N + col] : 0.f;
            }
        }
#pragma unroll
        for (int kk = 0; kk < 8; kk++) {
            float ar[8], br[8];
#pragma unroll
            for (int i = 0; i < 8; i++) ar[i] = As[p][kk][ty * 8 + i];
#pragma unroll
            for (int j = 0; j < 8; j++) br[j] = Bs[p][kk][tx * 8 + j];
#pragma unroll
            for (int i = 0; i < 8; i++)
#pragma unroll
                for (int j = 0; j < 8; j++)
                    acc[i][j] += ar[i] * br[j];
        }
        if (it + 1 < niter) {
#pragma unroll
            for (int u = 0; u < 4; u++) As[p ^ 1][a_c + u][a_r] = ra[u];
#pragma unroll
            for (int u = 0; u < 4; u++) Bs[p ^ 1][b_r][b_c + u] = rb[u];
        }
        __syncthreads();
    }

#pragma unroll
    for (int i = 0; i < 8; i++) {
        int row = block_row + ty * 8 + i;
#pragma unroll
        for (int j = 0; j < 8; j++) {
            int col = block_col + tx * 8 + j;
            if (col < N) {
                float v = acc[i][j] + bias[col];
                if (ACT) v = fast_tanh(v);
                C[(size_t)row * N + col] = v;
            }
        }
    }
}

// ---------------- thin GEMM for N <= 32 (double-buffered) --------------------
template <int ACT>
__global__ __launch_bounds__(256, 2)
void gemm_bias_act_thin(const float* __restrict__ A, const float* __restrict__ W,
                        const float* __restrict__ bias, float* __restrict__ C,
                        int N, int K, int rowbase)
{
    __shared__ float As[2][8][128];
    __shared__ float Bs[2][8][33];

    const int tid = threadIdx.x;
    const int block_row = rowbase + blockIdx.y * TT;
    const int tx = tid & 7, ty = tid >> 3;
    const int a_r = tid >> 1, a_c = (tid & 1) * 4;
    const int b_k = tid >> 5, b_c = tid & 31;

    const float* Arow = A + (size_t)(block_row + a_r) * K;

    float acc[4][4];
#pragma unroll
    for (int i = 0; i < 4; i++)
#pragma unroll
        for (int j = 0; j < 4; j++) acc[i][j] = 0.f;

    const int niter = (K + 7) / 8;
    float ra[4], rb;
    {
#pragma unroll
        for (int u = 0; u < 4; u++) { int k = a_c + u; ra[u] = (k < K) ? Arow[k] : 0.f; }
        rb = (b_k < K && b_c < N) ? W[(size_t)b_k * N + b_c] : 0.f;
#pragma unroll
        for (int u = 0; u < 4; u++) As[0][a_c + u][a_r] = ra[u];
        Bs[0][b_k][b_c] = rb;
    }
    __syncthreads();

    for (int it = 0; it < niter; it++) {
        const int p = it & 1;
        if (it + 1 < niter) {
            int k0 = (it + 1) * 8;
#pragma unroll
            for (int u = 0; u < 4; u++) { int k = k0 + a_c + u; ra[u] = (k < K) ? Arow[k] : 0.f; }
            int kb = k0 + b_k;
            rb = (kb < K && b_c < N) ? W[(size_t)kb * N + b_c] : 0.f;
        }
#pragma unroll
        for (int kk = 0; kk < 8; kk++) {
            float ar[4], br[4];
#pragma unroll
            for (int i = 0; i < 4; i++) ar[i] = As[p][kk][ty * 4 + i];
#pragma unroll
            for (int j = 0; j < 4; j++) br[j] = Bs[p][kk][tx * 4 + j];
#pragma unroll
            for (int i = 0; i < 4; i++)
#pragma unroll
                for (int j = 0; j < 4; j++)
                    acc[i][j] += ar[i] * br[j];
        }
        if (it + 1 < niter) {
#pragma unroll
            for (int u = 0; u < 4; u++) As[p ^ 1][a_c + u][a_r] = ra[u];
            Bs[p ^ 1][b_k][b_c] = rb;
        }
        __syncthreads();
    }

#pragma unroll
    for (int i = 0; i < 4; i++) {
        int row = block_row + ty * 4 + i;
#pragma unroll
        for (int j = 0; j < 4; j++) {
            int col = tx * 4 + j;
            if (col < N) {
                float v = acc[i][j] + bias[col];
                if (ACT) v = fast_tanh(v);
                C[(size_t)row * N + col] = v;
            }
        }
    }
}

// ================= sensory precompute (chunked): (wnum_s, wden_s)[b,t,j] =====
// grid = BB*TC/4 blocks; block covers 4 (b,t) rows of the chunk.
__global__ __launch_bounds__(256)
void sensory_pre(const float* __restrict__ h20, float2* __restrict__ sens,
                 const float* __restrict__ sw,   const float* __restrict__ smu,
                 const float* __restrict__ ssig, const float* __restrict__ serev,
                 const float* __restrict__ in_w, const float* __restrict__ in_b,
                 int tbase)
{
    __shared__ float sA[20][64], sB[20][64], sWe[20][64], sWr[20][64];
    __shared__ float hh[4][20];

    const int tid  = threadIdx.x;
    const int bpb  = TC / 4;                       // blocks per batch = 32
    const int bat  = blockIdx.x / bpb;
    const int wthn = blockIdx.x % bpb;
    const int bt0  = bat * TT + tbase + wthn * 4;

    for (int idx = tid; idx < 20 * 64; idx += 256) {
        int k = idx >> 6, j = idx & 63;
        float s_ = ssig[k * 64 + j];
        sA[k][j] = -in_w[k] * s_ * L2E;
        sB[k][j] = (smu[k * 64 + j] - in_b[k]) * s_ * L2E;
        float w_ = sw[k * 64 + j];
        sWr[k][j] = w_;
        sWe[k][j] = w_ * serev[k * 64 + j];
    }
    for (int idx = tid; idx < 80; idx += 256)
        hh[idx / 20][idx % 20] = h20[(size_t)bt0 * 20 + idx];
    __syncthreads();

    const int r = tid >> 6;
    const int j = tid & 63;
    float an = 0.f, ad = 0.f;
#pragma unroll
    for (int u = 0; u < 10; u++) {
        int k0 = 2 * u, k1 = 2 * u + 1;
        float a0 = fminf(fmaf(hh[r][k0], sA[k0][j], sB[k0][j]), 30.f);
        float a1 = fminf(fmaf(hh[r][k1], sA[k1][j], sB[k1][j]), 30.f);
        float q0 = 1.f + fast_ex2(a0);
        float q1 = 1.f + fast_ex2(a1);
        float rr = fast_rcp(q0 * q1);
        float nn = fmaf(sWe[k1][j], q0, sWe[k0][j] * q1);
        float dd = fmaf(sWr[k1][j], q0, sWr[k0][j] * q1);
        an = fmaf(rr, nn, an);
        ad = fmaf(rr, dd, ad);
    }
    sens[(size_t)(bt0 + r) * 64 + j] = make_float2(an, ad);
}

// ================= LTC scan chunk [t0, t1) — resumable =======================
__global__ __launch_bounds__(256)
void ltc_scan(const float2* __restrict__ sens, float* __restrict__ o4,
              float* __restrict__ vstate,
              const float* __restrict__ gleak, const float* __restrict__ vleak,
              const float* __restrict__ cm,    const float* __restrict__ w,
              const float* __restrict__ mu,    const float* __restrict__ sigma,
              const float* __restrict__ erev,
              const float* __restrict__ out_w, const float* __restrict__ out_b,
              int t0, int t1)
{
    __shared__ float sv[2][UNITS];

    const int b   = blockIdx.x;
    const int tid = threadIdx.x;
    const int j   = tid >> 2;
    const int q   = tid & 3;

    float ha[16], hb[16], we2[16], wr2[16];
    float cnum = 0.f, cden = 0.f;
#pragma unroll
    for (int m = 0; m < 16; m++) {
        int i   = q * 16 + m;
        int idx = i * UNITS + j;
        float s_ = sigma[idx];
        ha[m] = 0.5f * s_;
        hb[m] = 0.5f * mu[idx] * s_;
        float wv = 0.5f * w[idx];
        wr2[m] = wv;
        we2[m] = wv * erev[idx];
        cnum += we2[m];
        cden += wr2[m];
    }
#pragma unroll
    for (int off = 1; off < 4; off <<= 1) {
        cnum += __shfl_xor_sync(0xffffffffu, cnum, off);
        cden += __shfl_xor_sync(0xffffffffu, cden, off);
    }

    const float cmt    = cm[j] * (float)UNFOLDS;
    const float addnum = gleak[j] * vleak[j] + cnum;
    const float denbas = cmt + gleak[j] + cden + 1e-8f;
    float ow = 0.f, ob = 0.f;
    if (j < MOTOR) { ow = out_w[j]; ob = out_b[j]; }

    float vj;
    if (t0 == 0) {
        if (tid < UNITS) sv[0][tid] = 0.f;
        vj = 0.f;
    } else {
        if (tid < UNITS) sv[0][tid] = vstate[b * UNITS + tid];
        vj = vstate[b * UNITS + j];
    }
    __syncthreads();

    const float2* srow = sens + (size_t)b * TT * 64 + j;
    float2 wv = srow[(size_t)t0 * 64];

    int p = 0;

    for (int t = t0; t < t1; t++) {
        float2 wvn = (t + 1 < t1) ? srow[(size_t)(t + 1) * 64] : make_float2(0.f, 0.f);

#pragma unroll
        for (int uf = 0; uf < UNFOLDS; uf++) {
            const float4 v0 = *(const float4*)&sv[p][q * 16 + 0];
            const float4 v1 = *(const float4*)&sv[p][q * 16 + 4];
            const float4 v2 = *(const float4*)&sv[p][q * 16 + 8];
            const float4 v3 = *(const float4*)&sv[p][q * 16 + 12];
            float vr[16] = {v0.x, v0.y, v0.z, v0.w, v1.x, v1.y, v1.z, v1.w,
                            v2.x, v2.y, v2.z, v2.w, v3.x, v3.y, v3.z, v3.w};

            float an0 = 0.f, ad0 = 0.f, an1 = 0.f, ad1 = 0.f;
#pragma unroll
            for (int m = 0; m < 8; m++) {
                float t0_ = fast_tanh(fmaf(vr[m],     ha[m],     -hb[m]));
                float t1_ = fast_tanh(fmaf(vr[m + 8], ha[m + 8], -hb[m + 8]));
                an0 = fmaf(we2[m],     t0_, an0);
                ad0 = fmaf(wr2[m],     t0_, ad0);
                an1 = fmaf(we2[m + 8], t1_, an1);
                ad1 = fmaf(wr2[m + 8], t1_, ad1);
            }
            float an = an0 + an1, ad = ad0 + ad1;
#pragma unroll
            for (int off = 1; off < 4; off <<= 1) {
                an += __shfl_xor_sync(0xffffffffu, an, off);
                ad += __shfl_xor_sync(0xffffffffu, ad, off);
            }
            float num = fmaf(cmt, vj, addnum) + an + wv.x;
            float den = denbas + ad + wv.y;
            vj = num * fast_rcp(den);
            if (q == 0) sv[p ^ 1][j] = vj;
            __syncthreads();
            p ^= 1;
        }

        if (j < MOTOR && q == 0)
            o4[((size_t)b * TT + t) * MOTOR + j] = fmaf(vj, ow, ob);
        wv = wvn;
    }

    if (q == 0) vstate[b * UNITS + j] = vj;
}

// ---------------- pipeline resources (created once, before capture) ----------
struct PipeRes {
    cudaStream_t sE, sD;
    cudaEvent_t  root, evE[NCH], evS[NCH], evD;
    PipeRes() {
        cudaStreamCreateWithFlags(&sE, cudaStreamNonBlocking);
        cudaStreamCreateWithFlags(&sD, cudaStreamNonBlocking);
        cudaEventCreateWithFlags(&root, cudaEventDisableTiming);
        for (int i = 0; i < NCH; i++) {
            cudaEventCreateWithFlags(&evE[i], cudaEventDisableTiming);
            cudaEventCreateWithFlags(&evS[i], cudaEventDisableTiming);
        }
        cudaEventCreateWithFlags(&evD, cudaEventDisableTiming);
    }
};
static PipeRes g_pipe;

// ---------------- launcher ---------------------------------------------------
extern "C" void kernel_launch(void* const* d_in, const int* in_sizes, int n_in,
                              void* d_out, int out_size)
{
    const float* x     = (const float*)d_in[0];
    const float* ew0   = (const float*)d_in[1];
    const float* eb0   = (const float*)d_in[2];
    const float* ew1   = (const float*)d_in[3];
    const float* eb1   = (const float*)d_in[4];
    const float* ew2   = (const float*)d_in[5];
    const float* eb2   = (const float*)d_in[6];
    const float* dw0   = (const float*)d_in[7];
    const float* db0   = (const float*)d_in[8];
    const float* dw1   = (const float*)d_in[9];
    const float* db1   = (const float*)d_in[10];
    const float* dw2   = (const float*)d_in[11];
    const float* db2   = (const float*)d_in[12];
    const float* gleak = (const float*)d_in[13];
    const float* vleak = (const float*)d_in[14];
    const float* cm    = (const float*)d_in[15];
    const float* w     = (const float*)d_in[16];
    const float* mu    = (const float*)d_in[17];
    const float* sigma = (const float*)d_in[18];
    const float* erev  = (const float*)d_in[19];
    const float* sw    = (const float*)d_in[20];
    const float* smu   = (const float*)d_in[21];
    const float* ssig  = (const float*)d_in[22];
    const float* serev = (const float*)d_in[23];
    const float* in_w  = (const float*)d_in[24];
    const float* in_b  = (const float*)d_in[25];
    const float* out_w = (const float*)d_in[26];
    const float* out_b = (const float*)d_in[27];
    float* out = (float*)d_out;

    float *buf0, *buf1, *dbuf0, *dbuf1, *h20, *o4, *vst;
    float2* sens;
    cudaGetSymbolAddress((void**)&buf0,  g_buf0);
    cudaGetSymbolAddress((void**)&buf1,  g_buf1);
    cudaGetSymbolAddress((void**)&dbuf0, g_dbuf0);
    cudaGetSymbolAddress((void**)&dbuf1, g_dbuf1);
    cudaGetSymbolAddress((void**)&h20,   g_h20);
    cudaGetSymbolAddress((void**)&o4,    g_o4);
    cudaGetSymbolAddress((void**)&vst,   g_v);
    cudaGetSymbolAddress((void**)&sens,  g_sens);

    cudaStream_t sE = g_pipe.sE, sD = g_pipe.sD;

    dim3 blk(256);
    dim3 g500(4, BB);     // N=500, one 128-row tile per batch per chunk
    dim3 gthin(1, BB);

    // fork
    cudaEventRecord(g_pipe.root, 0);
    cudaStreamWaitEvent(sE, g_pipe.root, 0);
    cudaStreamWaitEvent(sD, g_pipe.root, 0);

    for (int c = 0; c < NCH; c++) {
        const int tb = c * TC;

        // ---- encoder chunk c (stream sE) ----
        gemm_bias_act<1><<<g500, blk, 0, sE>>>(x,    ew0, eb0, buf0, 500, 39, tb);
        gemm_tf32_tanh  <<<g500, blk, 0, sE>>>(buf0, ew1, eb1, buf1, 500, 500, tb);
        gemm_bias_act_thin<0><<<gthin, blk, 0, sE>>>(buf1, ew2, eb2, h20, 20, 500, tb);
        sensory_pre<<<BB * TC / 4, blk, 0, sE>>>(h20, sens, sw, smu, ssig, serev,
                                                 in_w, in_b, tb);
        cudaEventRecord(g_pipe.evE[c], sE);

        // ---- scan chunk c (main stream) ----
        cudaStreamWaitEvent(0, g_pipe.evE[c], 0);
        ltc_scan<<<BB, blk>>>(sens, o4, vst, gleak, vleak, cm, w, mu, sigma,
                              erev, out_w, out_b, tb, tb + TC);
        cudaEventRecord(g_pipe.evS[c], 0);

        // ---- decoder chunk c (stream sD) ----
        cudaStreamWaitEvent(sD, g_pipe.evS[c], 0);
        gemm_bias_act<1><<<g500, blk, 0, sD>>>(o4,    dw0, db0, dbuf0, 500, 4, tb);
        gemm_tf32_tanh  <<<g500, blk, 0, sD>>>(dbuf0, dw1, db1, dbuf1, 500, 500, tb);
        gemm_bias_act_thin<0><<<gthin, blk, 0, sD>>>(dbuf1, dw2, db2, out, 30, 500, tb);
    }

    // join
    cudaEventRecord(g_pipe.evD, sD);
    cudaStreamWaitEvent(0, g_pipe.evD, 0);
}

// round 13
// speedup vs baseline: 1.6446x; 1.1058x over previous
#include <cuda_runtime.h>

#define UNITS   64
#define TT      512
#define BB      32
#define MOTOR   4
#define UNFOLDS 6
#define MROWS   (BB*TT)      // 16384
#define NCH     4
#define TC      (TT/NCH)     // 128 timesteps per chunk
#define SCAN_SMEM_RESERVE (216*1024)   // SM-exclusivity fence for the scan

// ---------------- scratch (device globals: no allocation allowed) -----------
__device__ float  g_buf0[MROWS * 500];    // encoder intermediates
__device__ float  g_buf1[MROWS * 500];
__device__ float  g_dbuf0[MROWS * 500];   // decoder intermediates (separate:
__device__ float  g_dbuf1[MROWS * 500];   //  encoder/decoder chunks overlap)
__device__ float  g_h20 [MROWS * 20];
__device__ float  g_o4  [MROWS * 4];
__device__ float  g_v   [BB * UNITS];     // scan state between chunks
__device__ float2 g_sens[MROWS * UNITS];  // precomputed (wnum_s, wden_s)

__device__ __forceinline__ float fast_tanh(float x) {
    float r; asm("tanh.approx.f32 %0, %1;" : "=f"(r) : "f"(x)); return r;
}
__device__ __forceinline__ float fast_rcp(float x) {
    float r; asm("rcp.approx.f32 %0, %1;" : "=f"(r) : "f"(x)); return r;
}
__device__ __forceinline__ float fast_ex2(float x) {
    float r; asm("ex2.approx.f32 %0, %1;" : "=f"(r) : "f"(x)); return r;
}
__device__ __forceinline__ unsigned to_tf32(float x) {
    unsigned r; asm("cvt.rna.tf32.f32 %0, %1;" : "=r"(r) : "f"(x)); return r;
}

#define L2E 1.4426950408889634f

// ================= tf32 legacy-MMA GEMM: C = tanh(A@W + b) ===================
__device__ __forceinline__ void mma_tf32(float* d, const unsigned* a, const unsigned* b) {
    asm volatile(
        "mma.sync.aligned.m16n8k8.row.col.f32.tf32.tf32.f32 "
        "{%0,%1,%2,%3}, {%4,%5,%6,%7}, {%8,%9}, {%0,%1,%2,%3};"
        : "+f"(d[0]), "+f"(d[1]), "+f"(d[2]), "+f"(d[3])
        : "r"(a[0]), "r"(a[1]), "r"(a[2]), "r"(a[3]), "r"(b[0]), "r"(b[1]));
}

__global__ __launch_bounds__(256, 2)
void gemm_tf32_tanh(const float* __restrict__ A, const float* __restrict__ W,
                    const float* __restrict__ bias, float* __restrict__ C,
                    int N, int K, int rowbase)
{
    __shared__ float As[2][128][20];
    __shared__ float Bs[2][16][136];

    const int tid  = threadIdx.x;
    const int lane = tid & 31;
    const int warp = tid >> 5;
    const int warp_m = (warp >> 2) * 64;
    const int warp_n = (warp & 3) * 32;
    const int block_row = rowbase + blockIdx.y * TT;
    const int block_col = blockIdx.x * 128;

    const int a_r = tid >> 1;
    const int a_c = (tid & 1) * 8;
    const int b_k = tid >> 4;
    const int b_c = (tid & 15) * 8;

    const float* Arow = A + (size_t)(block_row + a_r) * K;

    float acc[4][4][4];
#pragma unroll
    for (int mt = 0; mt < 4; mt++)
#pragma unroll
        for (int nt = 0; nt < 4; nt++)
#pragma unroll
            for (int e = 0; e < 4; e++) acc[mt][nt][e] = 0.f;

    const int niter = (K + 15) / 16;
    float ra[8], rb[8];

#pragma unroll
    for (int u = 0; u < 8; u++) { int k = a_c + u; ra[u] = (k < K) ? Arow[k] : 0.f; }
#pragma unroll
    for (int u = 0; u < 8; u++) {
        int col = block_col + b_c + u;
        rb[u] = (b_k < K && col < N) ? W[(size_t)b_k * N + col] : 0.f;
    }
#pragma unroll
    for (int u = 0; u < 8; u++) As[0][a_r][a_c + u] = __uint_as_float(to_tf32(ra[u]));
#pragma unroll
    for (int u = 0; u < 8; u++) Bs[0][b_k][b_c + u] = __uint_as_float(to_tf32(rb[u]));
    __syncthreads();

    for (int it = 0; it < niter; it++) {
        const int s = it & 1;

        if (it + 1 < niter) {
            int k0 = (it + 1) * 16;
#pragma unroll
            for (int u = 0; u < 8; u++) { int k = k0 + a_c + u; ra[u] = (k < K) ? Arow[k] : 0.f; }
            int kb = k0 + b_k;
#pragma unroll
            for (int u = 0; u < 8; u++) {
                int col = block_col + b_c + u;
                rb[u] = (kb < K && col < N) ? W[(size_t)kb * N + col] : 0.f;
            }
        }

#pragma unroll
        for (int step = 0; step < 2; step++) {
            const int cb = step * 8;
            unsigned af[4][4], bf[4][2];
#pragma unroll
            for (int mt = 0; mt < 4; mt++) {
                int r0 = warp_m + mt * 16 + (lane >> 2);
                int c0 = cb + (lane & 3);
                af[mt][0] = __float_as_uint(As[s][r0][c0]);
                af[mt][1] = __float_as_uint(As[s][r0 + 8][c0]);
                af[mt][2] = __float_as_uint(As[s][r0][c0 + 4]);
                af[mt][3] = __float_as_uint(As[s][r0 + 8][c0 + 4]);
            }
#pragma unroll
            for (int nt = 0; nt < 4; nt++) {
                int n0 = warp_n + nt * 8 + (lane >> 2);
                bf[nt][0] = __float_as_uint(Bs[s][cb + (lane & 3)][n0]);
                bf[nt][1] = __float_as_uint(Bs[s][cb + (lane & 3) + 4][n0]);
            }
#pragma unroll
            for (int mt = 0; mt < 4; mt++)
#pragma unroll
                for (int nt = 0; nt < 4; nt++)
                    mma_tf32(acc[mt][nt], af[mt], bf[nt]);
        }

        if (it + 1 < niter) {
#pragma unroll
            for (int u = 0; u < 8; u++) As[s ^ 1][a_r][a_c + u] = __uint_as_float(to_tf32(ra[u]));
#pragma unroll
            for (int u = 0; u < 8; u++) Bs[s ^ 1][b_k][b_c + u] = __uint_as_float(to_tf32(rb[u]));
        }
        __syncthreads();
    }

#pragma unroll
    for (int mt = 0; mt < 4; mt++) {
        int r0 = block_row + warp_m + mt * 16 + (lane >> 2);
#pragma unroll
        for (int nt = 0; nt < 4; nt++) {
            int c0 = block_col + warp_n + nt * 8 + (lane & 3) * 2;
#pragma unroll
            for (int h = 0; h < 2; h++) {
                int rr = r0 + h * 8;
                float v0 = acc[mt][nt][h * 2 + 0];
                float v1 = acc[mt][nt][h * 2 + 1];
                if (c0 < N)     C[(size_t)rr * N + c0]     = fast_tanh(v0 + bias[c0]);
                if (c0 + 1 < N) C[(size_t)rr * N + c0 + 1] = fast_tanh(v1 + bias[c0 + 1]);
            }
        }
    }
}

// ---------------- SIMT fused GEMM (small-K layers) ---------------------------
template <int ACT>
__global__ __launch_bounds__(256, 2)
void gemm_bias_act(const float* __restrict__ A, const float* __restrict__ W,
                   const float* __restrict__ bias, float* __restrict__ C,
                   int N, int K, int rowbase)
{
    __shared__ float As[2][8][128];
    __shared__ float Bs[2][8][132];

    const int tid = threadIdx.x;
    const int block_row = rowbase + blockIdx.y * TT;
    const int block_col = blockIdx.x * 128;
    const int tx = tid & 15, ty = tid >> 4;
    const int a_r = tid >> 1, a_c = (tid & 1) * 4;
    const int b_r = tid >> 5, b_c = (tid & 31) * 4;

    const float* Arow = A + (size_t)(block_row + a_r) * K;

    float acc[8][8];
#pragma unroll
    for (int i = 0; i < 8; i++)
#pragma unroll
        for (int j = 0; j < 8; j++) acc[i][j] = 0.f;

    const int niter = (K + 7) / 8;
    float ra[4], rb[4];
    {
#pragma unroll
        for (int u = 0; u < 4; u++) { int k = a_c + u; ra[u] = (k < K) ? Arow[k] : 0.f; }
#pragma unroll
        for (int u = 0; u < 4; u++) {
            int col = block_col + b_c + u;
            rb[u] = (b_r < K && col < N) ? W[(size_t)b_r * N + col] : 0.f;
        }
#pragma unroll
        for (int u = 0; u < 4; u++) As[0][a_c + u][a_r] = ra[u];
#pragma unroll
        for (int u = 0; u < 4; u++) Bs[0][b_r][b_c + u] = rb[u];
    }
    __syncthreads();

    for (int it = 0; it < niter; it++) {
        const int p = it & 1;
        if (it + 1 < niter) {
            int k0 = (it + 1) * 8;
#pragma unroll
            for (int u = 0; u < 4; u++) { int k = k0 + a_c + u; ra[u] = (k < K) ? Arow[k] : 0.f; }
            int kb = k0 + b_r;
#pragma unroll
            for (int u = 0; u < 4; u++) {
                int col = block_col + b_c + u;
                rb[u] = (kb < K && col < N) ? W[(size_t)kb * N + col] : 0.f;
            }
        }
#pragma unroll
        for (int kk = 0; kk < 8; kk++) {
            float ar[8], br[8];
#pragma unroll
            for (int i = 0; i < 8; i++) ar[i] = As[p][kk][ty * 8 + i];
#pragma unroll
            for (int j = 0; j < 8; j++) br[j] = Bs[p][kk][tx * 8 + j];
#pragma unroll
            for (int i = 0; i < 8; i++)
#pragma unroll
                for (int j = 0; j < 8; j++)
                    acc[i][j] += ar[i] * br[j];
        }
        if (it + 1 < niter) {
#pragma unroll
            for (int u = 0; u < 4; u++) As[p ^ 1][a_c + u][a_r] = ra[u];
#pragma unroll
            for (int u = 0; u < 4; u++) Bs[p ^ 1][b_r][b_c + u] = rb[u];
        }
        __syncthreads();
    }

#pragma unroll
    for (int i = 0; i < 8; i++) {
        int row = block_row + ty * 8 + i;
#pragma unroll
        for (int j = 0; j < 8; j++) {
            int col = block_col + tx * 8 + j;
            if (col < N) {
                float v = acc[i][j] + bias[col];
                if (ACT) v = fast_tanh(v);
                C[(size_t)row * N + col] = v;
            }
        }
    }
}

// ---------------- thin GEMM for N <= 32 (double-buffered) --------------------
template <int ACT>
__global__ __launch_bounds__(256, 2)
void gemm_bias_act_thin(const float* __restrict__ A, const float* __restrict__ W,
                        const float* __restrict__ bias, float* __restrict__ C,
                        int N, int K, int rowbase)
{
    __shared__ float As[2][8][128];
    __shared__ float Bs[2][8][33];

    const int tid = threadIdx.x;
    const int block_row = rowbase + blockIdx.y * TT;
    const int tx = tid & 7, ty = tid >> 3;
    const int a_r = tid >> 1, a_c = (tid & 1) * 4;
    const int b_k = tid >> 5, b_c = tid & 31;

    const float* Arow = A + (size_t)(block_row + a_r) * K;

    float acc[4][4];
#pragma unroll
    for (int i = 0; i < 4; i++)
#pragma unroll
        for (int j = 0; j < 4; j++) acc[i][j] = 0.f;

    const int niter = (K + 7) / 8;
    float ra[4], rb;
    {
#pragma unroll
        for (int u = 0; u < 4; u++) { int k = a_c + u; ra[u] = (k < K) ? Arow[k] : 0.f; }
        rb = (b_k < K && b_c < N) ? W[(size_t)b_k * N + b_c] : 0.f;
#pragma unroll
        for (int u = 0; u < 4; u++) As[0][a_c + u][a_r] = ra[u];
        Bs[0][b_k][b_c] = rb;
    }
    __syncthreads();

    for (int it = 0; it < niter; it++) {
        const int p = it & 1;
        if (it + 1 < niter) {
            int k0 = (it + 1) * 8;
#pragma unroll
            for (int u = 0; u < 4; u++) { int k = k0 + a_c + u; ra[u] = (k < K) ? Arow[k] : 0.f; }
            int kb = k0 + b_k;
            rb = (kb < K && b_c < N) ? W[(size_t)kb * N + b_c] : 0.f;
        }
#pragma unroll
        for (int kk = 0; kk < 8; kk++) {
            float ar[4], br[4];
#pragma unroll
            for (int i = 0; i < 4; i++) ar[i] = As[p][kk][ty * 4 + i];
#pragma unroll
            for (int j = 0; j < 4; j++) br[j] = Bs[p][kk][tx * 4 + j];
#pragma unroll
            for (int i = 0; i < 4; i++)
#pragma unroll
                for (int j = 0; j < 4; j++)
                    acc[i][j] += ar[i] * br[j];
        }
        if (it + 1 < niter) {
#pragma unroll
            for (int u = 0; u < 4; u++) As[p ^ 1][a_c + u][a_r] = ra[u];
            Bs[p ^ 1][b_k][b_c] = rb;
        }
        __syncthreads();
    }

#pragma unroll
    for (int i = 0; i < 4; i++) {
        int row = block_row + ty * 4 + i;
#pragma unroll
        for (int j = 0; j < 4; j++) {
            int col = tx * 4 + j;
            if (col < N) {
                float v = acc[i][j] + bias[col];
                if (ACT) v = fast_tanh(v);
                C[(size_t)row * N + col] = v;
            }
        }
    }
}

// ================= sensory precompute (chunked): (wnum_s, wden_s)[b,t,j] =====
__global__ __launch_bounds__(256)
void sensory_pre(const float* __restrict__ h20, float2* __restrict__ sens,
                 const float* __restrict__ sw,   const float* __restrict__ smu,
                 const float* __restrict__ ssig, const float* __restrict__ serev,
                 const float* __restrict__ in_w, const float* __restrict__ in_b,
                 int tbase)
{
    __shared__ float sA[20][64], sB[20][64], sWe[20][64], sWr[20][64];
    __shared__ float hh[4][20];

    const int tid  = threadIdx.x;
    const int bpb  = TC / 4;
    const int bat  = blockIdx.x / bpb;
    const int wthn = blockIdx.x % bpb;
    const int bt0  = bat * TT + tbase + wthn * 4;

    for (int idx = tid; idx < 20 * 64; idx += 256) {
        int k = idx >> 6, j = idx & 63;
        float s_ = ssig[k * 64 + j];
        sA[k][j] = -in_w[k] * s_ * L2E;
        sB[k][j] = (smu[k * 64 + j] - in_b[k]) * s_ * L2E;
        float w_ = sw[k * 64 + j];
        sWr[k][j] = w_;
        sWe[k][j] = w_ * serev[k * 64 + j];
    }
    for (int idx = tid; idx < 80; idx += 256)
        hh[idx / 20][idx % 20] = h20[(size_t)bt0 * 20 + idx];
    __syncthreads();

    const int r = tid >> 6;
    const int j = tid & 63;
    float an = 0.f, ad = 0.f;
#pragma unroll
    for (int u = 0; u < 10; u++) {
        int k0 = 2 * u, k1 = 2 * u + 1;
        float a0 = fminf(fmaf(hh[r][k0], sA[k0][j], sB[k0][j]), 30.f);
        float a1 = fminf(fmaf(hh[r][k1], sA[k1][j], sB[k1][j]), 30.f);
        float q0 = 1.f + fast_ex2(a0);
        float q1 = 1.f + fast_ex2(a1);
        float rr = fast_rcp(q0 * q1);
        float nn = fmaf(sWe[k1][j], q0, sWe[k0][j] * q1);
        float dd = fmaf(sWr[k1][j], q0, sWr[k0][j] * q1);
        an = fmaf(rr, nn, an);
        ad = fmaf(rr, dd, ad);
    }
    sens[(size_t)(bt0 + r) * 64 + j] = make_float2(an, ad);
}

// ================= LTC scan chunk [t0, t1) — resumable, SM-exclusive =========
// The (unused) dynamic smem reservation blocks GEMM CTAs from co-residing on
// the scan's SMs, protecting its MUFU-floor critical path from issue-slot theft.
__global__ __launch_bounds__(256)
void ltc_scan(const float2* __restrict__ sens, float* __restrict__ o4,
              float* __restrict__ vstate,
              const float* __restrict__ gleak, const float* __restrict__ vleak,
              const float* __restrict__ cm,    const float* __restrict__ w,
              const float* __restrict__ mu,    const float* __restrict__ sigma,
              const float* __restrict__ erev,
              const float* __restrict__ out_w, const float* __restrict__ out_b,
              int t0, int t1)
{
    extern __shared__ float smem_fence[];   // unused; occupies the SM
    __shared__ float sv[2][UNITS];

    const int b   = blockIdx.x;
    const int tid = threadIdx.x;
    const int j   = tid >> 2;
    const int q   = tid & 3;

    float ha[16], hb[16], we2[16], wr2[16];
    float cnum = 0.f, cden = 0.f;
#pragma unroll
    for (int m = 0; m < 16; m++) {
        int i   = q * 16 + m;
        int idx = i * UNITS + j;
        float s_ = sigma[idx];
        ha[m] = 0.5f * s_;
        hb[m] = 0.5f * mu[idx] * s_;
        float wv = 0.5f * w[idx];
        wr2[m] = wv;
        we2[m] = wv * erev[idx];
        cnum += we2[m];
        cden += wr2[m];
    }
#pragma unroll
    for (int off = 1; off < 4; off <<= 1) {
        cnum += __shfl_xor_sync(0xffffffffu, cnum, off);
        cden += __shfl_xor_sync(0xffffffffu, cden, off);
    }

    const float cmt    = cm[j] * (float)UNFOLDS;
    const float addnum = gleak[j] * vleak[j] + cnum;
    const float denbas = cmt + gleak[j] + cden + 1e-8f;
    float ow = 0.f, ob = 0.f;
    if (j < MOTOR) { ow = out_w[j]; ob = out_b[j]; }

    float vj;
    if (t0 == 0) {
        if (tid < UNITS) sv[0][tid] = 0.f;
        vj = 0.f;
    } else {
        if (tid < UNITS) sv[0][tid] = vstate[b * UNITS + tid];
        vj = vstate[b * UNITS + j];
    }
    __syncthreads();

    const float2* srow = sens + (size_t)b * TT * 64 + j;
    float2 wv = srow[(size_t)t0 * 64];

    int p = 0;

    for (int t = t0; t < t1; t++) {
        float2 wvn = (t + 1 < t1) ? srow[(size_t)(t + 1) * 64] : make_float2(0.f, 0.f);

#pragma unroll
        for (int uf = 0; uf < UNFOLDS; uf++) {
            const float4 v0 = *(const float4*)&sv[p][q * 16 + 0];
            const float4 v1 = *(const float4*)&sv[p][q * 16 + 4];
            const float4 v2 = *(const float4*)&sv[p][q * 16 + 8];
            const float4 v3 = *(const float4*)&sv[p][q * 16 + 12];
            float vr[16] = {v0.x, v0.y, v0.z, v0.w, v1.x, v1.y, v1.z, v1.w,
                            v2.x, v2.y, v2.z, v2.w, v3.x, v3.y, v3.z, v3.w};

            float an0 = 0.f, ad0 = 0.f, an1 = 0.f, ad1 = 0.f;
#pragma unroll
            for (int m = 0; m < 8; m++) {
                float t0_ = fast_tanh(fmaf(vr[m],     ha[m],     -hb[m]));
                float t1_ = fast_tanh(fmaf(vr[m + 8], ha[m + 8], -hb[m + 8]));
                an0 = fmaf(we2[m],     t0_, an0);
                ad0 = fmaf(wr2[m],     t0_, ad0);
                an1 = fmaf(we2[m + 8], t1_, an1);
                ad1 = fmaf(wr2[m + 8], t1_, ad1);
            }
            float an = an0 + an1, ad = ad0 + ad1;
#pragma unroll
            for (int off = 1; off < 4; off <<= 1) {
                an += __shfl_xor_sync(0xffffffffu, an, off);
                ad += __shfl_xor_sync(0xffffffffu, ad, off);
            }
            float num = fmaf(cmt, vj, addnum) + an + wv.x;
            float den = denbas + ad + wv.y;
            vj = num * fast_rcp(den);
            if (q == 0) sv[p ^ 1][j] = vj;
            __syncthreads();
            p ^= 1;
        }

        if (j < MOTOR && q == 0)
            o4[((size_t)b * TT + t) * MOTOR + j] = fmaf(vj, ow, ob);
        wv = wvn;
    }

    if (q == 0) vstate[b * UNITS + j] = vj;
}

// ---------------- pipeline resources (created once, before capture) ----------
struct PipeRes {
    cudaStream_t sE, sD;
    cudaEvent_t  root, evE[NCH], evS[NCH], evD;
    PipeRes() {
        cudaStreamCreateWithFlags(&sE, cudaStreamNonBlocking);
        cudaStreamCreateWithFlags(&sD, cudaStreamNonBlocking);
        cudaEventCreateWithFlags(&root, cudaEventDisableTiming);
        for (int i = 0; i < NCH; i++) {
            cudaEventCreateWithFlags(&evE[i], cudaEventDisableTiming);
            cudaEventCreateWithFlags(&evS[i], cudaEventDisableTiming);
        }
        cudaEventCreateWithFlags(&evD, cudaEventDisableTiming);
        cudaFuncSetAttribute(ltc_scan, cudaFuncAttributeMaxDynamicSharedMemorySize,
                             SCAN_SMEM_RESERVE);
    }
};
static PipeRes g_pipe;

// ---------------- launcher ---------------------------------------------------
extern "C" void kernel_launch(void* const* d_in, const int* in_sizes, int n_in,
                              void* d_out, int out_size)
{
    const float* x     = (const float*)d_in[0];
    const float* ew0   = (const float*)d_in[1];
    const float* eb0   = (const float*)d_in[2];
    const float* ew1   = (const float*)d_in[3];
    const float* eb1   = (const float*)d_in[4];
    const float* ew2   = (const float*)d_in[5];
    const float* eb2   = (const float*)d_in[6];
    const float* dw0   = (const float*)d_in[7];
    const float* db0   = (const float*)d_in[8];
    const float* dw1   = (const float*)d_in[9];
    const float* db1   = (const float*)d_in[10];
    const float* dw2   = (const float*)d_in[11];
    const float* db2   = (const float*)d_in[12];
    const float* gleak = (const float*)d_in[13];
    const float* vleak = (const float*)d_in[14];
    const float* cm    = (const float*)d_in[15];
    const float* w     = (const float*)d_in[16];
    const float* mu    = (const float*)d_in[17];
    const float* sigma = (const float*)d_in[18];
    const float* erev  = (const float*)d_in[19];
    const float* sw    = (const float*)d_in[20];
    const float* smu   = (const float*)d_in[21];
    const float* ssig  = (const float*)d_in[22];
    const float* serev = (const float*)d_in[23];
    const float* in_w  = (const float*)d_in[24];
    const float* in_b  = (const float*)d_in[25];
    const float* out_w = (const float*)d_in[26];
    const float* out_b = (const float*)d_in[27];
    float* out = (float*)d_out;

    float *buf0, *buf1, *dbuf0, *dbuf1, *h20, *o4, *vst;
    float2* sens;
    cudaGetSymbolAddress((void**)&buf0,  g_buf0);
    cudaGetSymbolAddress((void**)&buf1,  g_buf1);
    cudaGetSymbolAddress((void**)&dbuf0, g_dbuf0);
    cudaGetSymbolAddress((void**)&dbuf1, g_dbuf1);
    cudaGetSymbolAddress((void**)&h20,   g_h20);
    cudaGetSymbolAddress((void**)&o4,    g_o4);
    cudaGetSymbolAddress((void**)&vst,   g_v);
    cudaGetSymbolAddress((void**)&sens,  g_sens);

    // idempotent (also done in PipeRes ctor; harmless under capture)
    cudaFuncSetAttribute(ltc_scan, cudaFuncAttributeMaxDynamicSharedMemorySize,
                         SCAN_SMEM_RESERVE);

    cudaStream_t sE = g_pipe.sE, sD = g_pipe.sD;

    dim3 blk(256);
    dim3 g500(4, BB);
    dim3 gthin(1, BB);

    // fork
    cudaEventRecord(g_pipe.root, 0);
    cudaStreamWaitEvent(sE, g_pipe.root, 0);
    cudaStreamWaitEvent(sD, g_pipe.root, 0);

    for (int c = 0; c < NCH; c++) {
        const int tb = c * TC;

        // ---- encoder chunk c (stream sE) ----
        gemm_bias_act<1><<<g500, blk, 0, sE>>>(x,    ew0, eb0, buf0, 500, 39, tb);
        gemm_tf32_tanh  <<<g500, blk, 0, sE>>>(buf0, ew1, eb1, buf1, 500, 500, tb);
        gemm_bias_act_thin<0><<<gthin, blk, 0, sE>>>(buf1, ew2, eb2, h20, 20, 500, tb);
        sensory_pre<<<BB * TC / 4, blk, 0, sE>>>(h20, sens, sw, smu, ssig, serev,
                                                 in_w, in_b, tb);
        cudaEventRecord(g_pipe.evE[c], sE);

        // ---- scan chunk c (main stream, SM-exclusive via smem reservation) ----
        cudaStreamWaitEvent(0, g_pipe.evE[c], 0);
        ltc_scan<<<BB, blk, SCAN_SMEM_RESERVE>>>(sens, o4, vst, gleak, vleak, cm,
                                                 w, mu, sigma, erev, out_w, out_b,
                                                 tb, tb + TC);
        cudaEventRecord(g_pipe.evS[c], 0);

        // ---- decoder chunk c (stream sD) ----
        cudaStreamWaitEvent(sD, g_pipe.evS[c], 0);
        gemm_bias_act<1><<<g500, blk, 0, sD>>>(o4,    dw0, db0, dbuf0, 500, 4, tb);
        gemm_tf32_tanh  <<<g500, blk, 0, sD>>>(dbuf0, dw1, db1, dbuf1, 500, 500, tb);
        gemm_bias_act_thin<0><<<gthin, blk, 0, sD>>>(dbuf1, dw2, db2, out, 30, 500, tb);
    }

    // join
    cudaEventRecord(g_pipe.evD, sD);
    cudaStreamWaitEvent(0, g_pipe.evD, 0);
}